// round 4
// baseline (speedup 1.0000x reference)
#include <cuda_runtime.h>
#include <math.h>
#include <stdint.h>

#define T_TOK 2048
#define HDIM  1024
#define FFND  4096
#define NE    8
#define NF2   8192   // 2*FFND
#define NPAIR (2*T_TOK)

// ---------------- scratch (static device globals; no allocation) ------------
__device__ int   d_count[NE];
__device__ int   d_list[NE * T_TOK];      // packed (token*2 + kslot)
__device__ float d_wgt[NPAIR];            // weight per (token,kslot)
__device__ float d_z[(size_t)NPAIR * NF2];       // [pair, 8192] g|u
__device__ float d_actbuf[(size_t)NPAIR * FFND]; // silu(g)*u
__device__ float d_y[(size_t)NPAIR * HDIM];      // per-pair down-proj

// ---------------------------------------------------------------------------
__global__ void zero_counts_kernel() {
    if (threadIdx.x < NE) d_count[threadIdx.x] = 0;
}

// One warp per token: router logits, top-2 softmax weights, expert compaction.
__global__ void router_kernel(const float* __restrict__ x,
                              const float* __restrict__ gw,
                              float* __restrict__ rlogits) {
    int gwarp = (blockIdx.x * blockDim.x + threadIdx.x) >> 5;
    int lane  = threadIdx.x & 31;
    if (gwarp >= T_TOK) return;
    const float* xr = x + (size_t)gwarp * HDIM;

    float acc[NE];
#pragma unroll
    for (int e = 0; e < NE; e++) acc[e] = 0.f;
    for (int h = lane; h < HDIM; h += 32) {
        float xv = xr[h];
#pragma unroll
        for (int e = 0; e < NE; e++) acc[e] += xv * gw[e * HDIM + h];
    }
#pragma unroll
    for (int e = 0; e < NE; e++)
#pragma unroll
        for (int off = 16; off; off >>= 1)
            acc[e] += __shfl_xor_sync(0xffffffffu, acc[e], off);

    if (lane == 0) {
#pragma unroll
        for (int e = 0; e < NE; e++) rlogits[gwarp * NE + e] = acc[e];
        int e0 = 0;
#pragma unroll
        for (int e = 1; e < NE; e++) if (acc[e] > acc[e0]) e0 = e;
        int e1 = (e0 == 0) ? 1 : 0;
#pragma unroll
        for (int e = 0; e < NE; e++)
            if (e != e0 && acc[e] > acc[e1]) e1 = e;
        float p1 = __expf(acc[e1] - acc[e0]);
        float inv = 1.0f / (1.0f + p1);
        d_wgt[gwarp * 2 + 0] = inv;
        d_wgt[gwarp * 2 + 1] = p1 * inv;

        int pos0 = atomicAdd(&d_count[e0], 1);
        d_list[e0 * T_TOK + pos0] = gwarp * 2 + 0;
        int pos1 = atomicAdd(&d_count[e1], 1);
        d_list[e1 * T_TOK + pos1] = gwarp * 2 + 1;
    }
}

// ---------------- tf32 helpers ----------------------------------------------
__device__ __forceinline__ uint32_t f2tf32(float f) {
    uint32_t r;
    asm("cvt.rna.tf32.f32 %0, %1;" : "=r"(r) : "f"(f));
    return r;
}

__device__ __forceinline__ void mma_tf32(float* d, const uint32_t* a, const uint32_t* b) {
    asm volatile(
        "mma.sync.aligned.m16n8k8.row.col.f32.tf32.tf32.f32 "
        "{%0,%1,%2,%3}, {%4,%5,%6,%7}, {%8,%9}, {%0,%1,%2,%3};\n"
        : "+f"(d[0]), "+f"(d[1]), "+f"(d[2]), "+f"(d[3])
        : "r"(a[0]), "r"(a[1]), "r"(a[2]), "r"(a[3]), "r"(b[0]), "r"(b[1]));
}

// ---------------- GEMM1 (tensor core, conservative) --------------------------
// z[pair, n0..] = x[token(pair)] . w13[e][n]^T, K = HDIM = 1024.
// 128x128 block tile, BK=32, 256 threads = 8 warps (2x4), warp tile 64x32.
// Scalar SMEM traffic only; tf32 conversion at SMEM-store; no prefetch.
__global__ __launch_bounds__(256)
void gemm1_mma_kernel(const float* __restrict__ A, const float* __restrict__ Bw) {
    int e   = blockIdx.z;
    int cnt = d_count[e];
    int m0  = blockIdx.x * 128;
    if (m0 >= cnt) return;
    int n0  = blockIdx.y * 128;

    __shared__ float As[128][33];
    __shared__ float Bs[128][33];
    __shared__ int   sPair[128];

    int tid = threadIdx.x;
    if (tid < 128) {
        int m = m0 + tid;
        sPair[tid] = d_list[e * T_TOK + (m < cnt ? m : cnt - 1)];
    }
    __syncthreads();

    int warp = tid >> 5;
    int lane = tid & 31;
    int wm = warp & 1;            // 64-row slab
    int wn = warp >> 1;           // 32-col slab
    int g  = lane >> 2;           // 0..7
    int tg = lane & 3;            // 0..3

    float acc[4][4][4];
#pragma unroll
    for (int i = 0; i < 4; i++)
#pragma unroll
        for (int j = 0; j < 4; j++)
#pragma unroll
            for (int r = 0; r < 4; r++) acc[i][j][r] = 0.f;

    for (int kc = 0; kc < HDIM; kc += 32) {
        // Load 128x32 A and B tiles, 16 scalars per thread each, coalesced per warp.
#pragma unroll
        for (int i = 0; i < 16; i++) {
            int idx = tid + i * 256;
            int r = idx >> 5, c = idx & 31;
            float av = A[(size_t)(sPair[r] >> 1) * HDIM + kc + c];
            float bv = Bw[((size_t)e * NF2 + n0 + r) * HDIM + kc + c];
            As[r][c] = __uint_as_float(f2tf32(av));
            Bs[r][c] = __uint_as_float(f2tf32(bv));
        }
        __syncthreads();

#pragma unroll
        for (int s = 0; s < 4; s++) {
            int k0 = s * 8 + tg;
            uint32_t afr[4][4], bfr[4][2];
#pragma unroll
            for (int i = 0; i < 4; i++) {
                int r0 = wm * 64 + i * 16 + g;
                afr[i][0] = __float_as_uint(As[r0][k0]);
                afr[i][1] = __float_as_uint(As[r0 + 8][k0]);
                afr[i][2] = __float_as_uint(As[r0][k0 + 4]);
                afr[i][3] = __float_as_uint(As[r0 + 8][k0 + 4]);
            }
#pragma unroll
            for (int j = 0; j < 4; j++) {
                int n = wn * 32 + j * 8 + g;
                bfr[j][0] = __float_as_uint(Bs[n][k0]);
                bfr[j][1] = __float_as_uint(Bs[n][k0 + 4]);
            }
#pragma unroll
            for (int i = 0; i < 4; i++)
#pragma unroll
                for (int j = 0; j < 4; j++)
                    mma_tf32(acc[i][j], afr[i], bfr[j]);
        }
        __syncthreads();
    }

    // Fully-guarded scalar epilogue.
#pragma unroll
    for (int i = 0; i < 4; i++) {
#pragma unroll
        for (int rr = 0; rr < 2; rr++) {
            int mloc = wm * 64 + i * 16 + rr * 8 + g;
            if (m0 + mloc < cnt) {
                int p = sPair[mloc];
                float* dst = d_z + (size_t)p * NF2 + n0 + wn * 32;
#pragma unroll
                for (int j = 0; j < 4; j++) {
                    dst[j * 8 + tg * 2 + 0] = acc[i][j][rr * 2 + 0];
                    dst[j * 8 + tg * 2 + 1] = acc[i][j][rr * 2 + 1];
                }
            }
        }
    }
}

// ---------------- act: silu(g) * u  (float4) --------------------------------
__global__ void act_kernel() {
    int i4 = blockIdx.x * blockDim.x + threadIdx.x;       // over NPAIR*FFND/4
    int p  = i4 >> 10;                                    // / (FFND/4)
    int f4 = i4 & 1023;
    if (p >= NPAIR) return;
    const float4* gp = (const float4*)(d_z + (size_t)p * NF2) + f4;
    const float4* up = (const float4*)(d_z + (size_t)p * NF2 + FFND) + f4;
    float4 gv = *gp, uv = *up, r;
    r.x = gv.x / (1.0f + __expf(-gv.x)) * uv.x;
    r.y = gv.y / (1.0f + __expf(-gv.y)) * uv.y;
    r.z = gv.z / (1.0f + __expf(-gv.z)) * uv.z;
    r.w = gv.w / (1.0f + __expf(-gv.w)) * uv.w;
    ((float4*)(d_actbuf + (size_t)p * FFND))[f4] = r;
}

// ---------------- GEMM2 (SIMT fp32, known-good R1 version) ------------------
__global__ __launch_bounds__(256, 2)
void gemm2_kernel(const float* __restrict__ w2) {
    int e   = blockIdx.z;
    int cnt = d_count[e];
    int m0  = blockIdx.x * 128;
    if (m0 >= cnt) return;
    int n0  = blockIdx.y * 128;   // over HDIM (8 tiles)

    __shared__ float As[8][128];
    __shared__ float Bs[8][128];
    __shared__ int   sPair[128];

    int tid = threadIdx.x;
    if (tid < 128) {
        int m = m0 + tid;
        sPair[tid] = d_list[e * T_TOK + (m < cnt ? m : m0)];
    }
    __syncthreads();

    int aRow = tid >> 1;
    int aC   = (tid & 1) * 4;
    const float* aSrc = d_actbuf + (size_t)sPair[aRow] * FFND + aC;
    const float* bSrc = w2 + ((size_t)e * HDIM + n0 + aRow) * FFND + aC;

    float acc[8][8];
#pragma unroll
    for (int i = 0; i < 8; i++)
#pragma unroll
        for (int j = 0; j < 8; j++) acc[i][j] = 0.f;

    int tr = tid >> 4, tc = tid & 15;

    for (int k0 = 0; k0 < FFND; k0 += 8) {
        float4 av = *(const float4*)(aSrc + k0);
        float4 bv = *(const float4*)(bSrc + k0);
        As[aC + 0][aRow] = av.x; As[aC + 1][aRow] = av.y;
        As[aC + 2][aRow] = av.z; As[aC + 3][aRow] = av.w;
        Bs[aC + 0][aRow] = bv.x; Bs[aC + 1][aRow] = bv.y;
        Bs[aC + 2][aRow] = bv.z; Bs[aC + 3][aRow] = bv.w;
        __syncthreads();
#pragma unroll
        for (int k = 0; k < 8; k++) {
            float a[8], b[8];
            *(float4*)(a)     = *(const float4*)&As[k][tr * 8];
            *(float4*)(a + 4) = *(const float4*)&As[k][tr * 8 + 4];
            *(float4*)(b)     = *(const float4*)&Bs[k][tc * 8];
            *(float4*)(b + 4) = *(const float4*)&Bs[k][tc * 8 + 4];
#pragma unroll
            for (int i = 0; i < 8; i++)
#pragma unroll
                for (int j = 0; j < 8; j++) acc[i][j] += a[i] * b[j];
        }
        __syncthreads();
    }

#pragma unroll
    for (int i = 0; i < 8; i++) {
        int mloc = tr * 8 + i;
        if (m0 + mloc < cnt) {
            int p = sPair[mloc];
            float* dst = d_y + (size_t)p * HDIM + n0 + tc * 8;
            *(float4*)(dst)     = *(float4*)&acc[i][0];
            *(float4*)(dst + 4) = *(float4*)&acc[i][4];
        }
    }
}

// ---------------- combine: out[t] = w0*y[2t] + w1*y[2t+1] -------------------
__global__ void combine_kernel(float* __restrict__ out) {
    int i4 = blockIdx.x * blockDim.x + threadIdx.x;   // over T*H/4
    int t  = i4 >> 8;                                 // / (HDIM/4)
    int h4 = i4 & 255;
    if (t >= T_TOK) return;
    float w0 = d_wgt[2 * t], w1 = d_wgt[2 * t + 1];
    const float4* y0 = (const float4*)(d_y + (size_t)(2 * t) * HDIM) + h4;
    const float4* y1 = (const float4*)(d_y + (size_t)(2 * t + 1) * HDIM) + h4;
    float4 a = *y0, b = *y1, r;
    r.x = w0 * a.x + w1 * b.x;
    r.y = w0 * a.y + w1 * b.y;
    r.z = w0 * a.z + w1 * b.z;
    r.w = w0 * a.w + w1 * b.w;
    ((float4*)(out + (size_t)t * HDIM))[h4] = r;
}

// ---------------------------------------------------------------------------
extern "C" void kernel_launch(void* const* d_in, const int* in_sizes, int n_in,
                              void* d_out, int out_size) {
    const float* x   = (const float*)d_in[0];  // [2048, 1024]
    const float* gw  = (const float*)d_in[1];  // [8, 1024]
    const float* w13 = (const float*)d_in[2];  // [8, 8192, 1024]
    const float* w2  = (const float*)d_in[3];  // [8, 1024, 4096]
    float* out = (float*)d_out;                // [2048*1024] then [2048*8]
    float* rlogits = out + (size_t)T_TOK * HDIM;

    zero_counts_kernel<<<1, 32>>>();
    router_kernel<<<T_TOK / 8, 256>>>(x, gw, rlogits);

    // GEMM1 (tensor core): z[pair, 0..8192) = x[token] . w13[e]^T, K=1024
    dim3 g1(T_TOK / 128, NF2 / 128, NE);      // (16, 64, 8)
    gemm1_mma_kernel<<<g1, 256>>>(x, w13);

    act_kernel<<<(NPAIR * FFND / 4) / 256, 256>>>();

    // GEMM2 (SIMT fp32): y[pair, 0..1024) = act[pair] . w2[e]^T, K=4096
    dim3 g2(T_TOK / 128, HDIM / 128, NE);     // (16, 8, 8)
    gemm2_kernel<<<g2, 256>>>(w2);

    combine_kernel<<<(T_TOK * HDIM / 4) / 256, 256>>>(out);
}

// round 5
// speedup vs baseline: 5.9962x; 5.9962x over previous
#include <cuda_runtime.h>
#include <math.h>
#include <stdint.h>

#define T_TOK 2048
#define HDIM  1024
#define FFND  4096
#define NE    8
#define NF2   8192   // 2*FFND
#define NPAIR (2*T_TOK)

// ---------------- scratch (static device globals; no allocation) ------------
// NOTE: never pass these as kernel arguments from host — host-side symbol
// shadows are not device pointers. Kernels reference them directly.
__device__ int   d_count[NE];
__device__ int   d_list[NE * T_TOK];      // packed (token*2 + kslot)
__device__ float d_wgt[NPAIR];            // weight per (token,kslot)
__device__ float d_z[(size_t)NPAIR * NF2];       // [pair, 8192] g|u
__device__ float d_actbuf[(size_t)NPAIR * FFND]; // silu(g)*u
__device__ float d_y[(size_t)NPAIR * HDIM];      // per-pair down-proj

// ---------------------------------------------------------------------------
__global__ void zero_counts_kernel() {
    if (threadIdx.x < NE) d_count[threadIdx.x] = 0;
}

// One warp per token: router logits, top-2 softmax weights, expert compaction.
__global__ void router_kernel(const float* __restrict__ x,
                              const float* __restrict__ gw,
                              float* __restrict__ rlogits) {
    int gwarp = (blockIdx.x * blockDim.x + threadIdx.x) >> 5;
    int lane  = threadIdx.x & 31;
    if (gwarp >= T_TOK) return;
    const float* xr = x + (size_t)gwarp * HDIM;

    float acc[NE];
#pragma unroll
    for (int e = 0; e < NE; e++) acc[e] = 0.f;
    for (int h = lane; h < HDIM; h += 32) {
        float xv = xr[h];
#pragma unroll
        for (int e = 0; e < NE; e++) acc[e] += xv * gw[e * HDIM + h];
    }
#pragma unroll
    for (int e = 0; e < NE; e++)
#pragma unroll
        for (int off = 16; off; off >>= 1)
            acc[e] += __shfl_xor_sync(0xffffffffu, acc[e], off);

    if (lane == 0) {
#pragma unroll
        for (int e = 0; e < NE; e++) rlogits[gwarp * NE + e] = acc[e];
        int e0 = 0;
#pragma unroll
        for (int e = 1; e < NE; e++) if (acc[e] > acc[e0]) e0 = e;
        int e1 = (e0 == 0) ? 1 : 0;
#pragma unroll
        for (int e = 0; e < NE; e++)
            if (e != e0 && acc[e] > acc[e1]) e1 = e;
        float p1 = __expf(acc[e1] - acc[e0]);
        float inv = 1.0f / (1.0f + p1);
        d_wgt[gwarp * 2 + 0] = inv;
        d_wgt[gwarp * 2 + 1] = p1 * inv;

        int pos0 = atomicAdd(&d_count[e0], 1);
        d_list[e0 * T_TOK + pos0] = gwarp * 2 + 0;
        int pos1 = atomicAdd(&d_count[e1], 1);
        d_list[e1 * T_TOK + pos1] = gwarp * 2 + 1;
    }
}

// ---------------- tf32 helpers ----------------------------------------------
__device__ __forceinline__ uint32_t f2tf32(float f) {
    uint32_t r;
    asm("cvt.rna.tf32.f32 %0, %1;" : "=r"(r) : "f"(f));
    return r;
}

__device__ __forceinline__ void mma_tf32(float* d, const uint32_t* a, const uint32_t* b) {
    asm volatile(
        "mma.sync.aligned.m16n8k8.row.col.f32.tf32.tf32.f32 "
        "{%0,%1,%2,%3}, {%4,%5,%6,%7}, {%8,%9}, {%0,%1,%2,%3};\n"
        : "+f"(d[0]), "+f"(d[1]), "+f"(d[2]), "+f"(d[3])
        : "r"(a[0]), "r"(a[1]), "r"(a[2]), "r"(a[3]), "r"(b[0]), "r"(b[1]));
}

__device__ __forceinline__ void ldsm_x4(uint32_t* r, uint32_t addr) {
    asm volatile("ldmatrix.sync.aligned.m8n8.x4.shared.b16 {%0,%1,%2,%3}, [%4];"
                 : "=r"(r[0]), "=r"(r[1]), "=r"(r[2]), "=r"(r[3]) : "r"(addr));
}
__device__ __forceinline__ void ldsm_x2(uint32_t* r, uint32_t addr) {
    asm volatile("ldmatrix.sync.aligned.m8n8.x2.shared.b16 {%0,%1}, [%2];"
                 : "=r"(r[0]), "=r"(r[1]) : "r"(addr));
}

// ---------------- tensor-core GEMM ------------------------------------------
// C[pair, n0..] = A_row(pair) . B[e][n]^T ; 128x128 block tile, BK=32,
// 256 threads = 8 warps (2x4), warp tile 64x32, m16n8k8 tf32 MMA atoms.
// MODE 0: A = Aarg (x, row = pair>>1), C = d_z (stride NF2)      [gemm1]
// MODE 1: A = d_actbuf (row = pair),   C = d_y (stride HDIM)     [gemm2]
template<int KDIM, int BROWS, int MODE>
__global__ __launch_bounds__(256)
void mma_gemm_kernel(const float* __restrict__ Aarg, const float* __restrict__ Bw) {
    const float* A = (MODE == 0) ? Aarg : d_actbuf;
    float* C       = (MODE == 0) ? d_z  : d_y;
    const int CLD    = (MODE == 0) ? NF2 : HDIM;
    const int ASHIFT = (MODE == 0) ? 1 : 0;

    int e   = blockIdx.z;
    int cnt = d_count[e];
    int m0  = blockIdx.x * 128;
    if (m0 >= cnt) return;
    int n0  = blockIdx.y * 128;

    __shared__ float As[128][36];   // row stride 144B = 9x16B -> LDSM conflict-free
    __shared__ float Bs[128][36];
    __shared__ int   sPair[128];

    int tid = threadIdx.x;
    if (tid < 128) {
        int m = m0 + tid;
        sPair[tid] = d_list[e * T_TOK + (m < cnt ? m : cnt - 1)];
    }
    __syncthreads();

    int row  = tid >> 1;          // 0..127
    int hc   = (tid & 1) * 16;    // k-col offset 0/16

    const float* aPtr = A  + (size_t)(sPair[row] >> ASHIFT) * KDIM + hc;
    const float* bPtr = Bw + ((size_t)e * BROWS + n0 + row) * KDIM + hc;

    int warp = tid >> 5;
    int lane = tid & 31;
    int wm = warp & 1;            // 64-row slab
    int wn = warp >> 1;           // 32-col slab
    int g  = lane >> 2;           // 0..7
    int tg = lane & 3;            // 0..3

    // ldmatrix lane->address mapping (A: x4 over 16x8 tf32 tile as 16x16 b16)
    int aSub = lane >> 3;                       // 0..3
    int aRowSel = ((aSub & 1) << 3) + (lane & 7);
    int aColSel = (aSub >> 1) << 2;             // 0 or 4
    // B: x2 over 8x8 tf32 tile as 8x16 b16
    int bRowSel = lane & 7;
    int bColSel = ((lane >> 3) & 1) << 2;       // 0 or 4

    uint32_t sAs = (uint32_t)__cvta_generic_to_shared(&As[0][0]);
    uint32_t sBs = (uint32_t)__cvta_generic_to_shared(&Bs[0][0]);
    uint32_t aBase = sAs + ((wm * 64 + aRowSel) * 36 + aColSel) * 4u;
    uint32_t bBase = sBs + ((wn * 32 + bRowSel) * 36 + bColSel) * 4u;

    float acc[4][4][4];
#pragma unroll
    for (int i = 0; i < 4; i++)
#pragma unroll
        for (int j = 0; j < 4; j++)
#pragma unroll
            for (int r = 0; r < 4; r++) acc[i][j][r] = 0.f;

    float4 fa[4], fb[4];
#pragma unroll
    for (int q = 0; q < 4; q++) {
        fa[q] = *(const float4*)(aPtr + q * 4);
        fb[q] = *(const float4*)(bPtr + q * 4);
    }

    const int NCHUNK = KDIM / 32;
    for (int kc = 0; kc < NCHUNK; kc++) {
        // store fetched chunk to SMEM as tf32 bit patterns (vectorized, aligned)
#pragma unroll
        for (int q = 0; q < 4; q++) {
            uint4 ua, ub;
            ua.x = f2tf32(fa[q].x); ua.y = f2tf32(fa[q].y);
            ua.z = f2tf32(fa[q].z); ua.w = f2tf32(fa[q].w);
            ub.x = f2tf32(fb[q].x); ub.y = f2tf32(fb[q].y);
            ub.z = f2tf32(fb[q].z); ub.w = f2tf32(fb[q].w);
            *(uint4*)&As[row][hc + q * 4] = ua;
            *(uint4*)&Bs[row][hc + q * 4] = ub;
        }
        __syncthreads();

        if (kc + 1 < NCHUNK) {
            const float* ap = aPtr + (kc + 1) * 32;
            const float* bp = bPtr + (kc + 1) * 32;
#pragma unroll
            for (int q = 0; q < 4; q++) {
                fa[q] = *(const float4*)(ap + q * 4);
                fb[q] = *(const float4*)(bp + q * 4);
            }
        }

#pragma unroll
        for (int s = 0; s < 4; s++) {
            uint32_t afr[4][4], bfr[4][2];
#pragma unroll
            for (int i = 0; i < 4; i++)
                ldsm_x4(afr[i], aBase + (i * 16 * 36 + s * 8) * 4u);
#pragma unroll
            for (int j = 0; j < 4; j++)
                ldsm_x2(bfr[j], bBase + (j * 8 * 36 + s * 8) * 4u);
#pragma unroll
            for (int i = 0; i < 4; i++)
#pragma unroll
                for (int j = 0; j < 4; j++)
                    mma_tf32(acc[i][j], afr[i], bfr[j]);
        }
        __syncthreads();
    }

    // epilogue: rows g, g+8 of each 16-row atom; cols tg*2, tg*2+1 per 8-col atom
#pragma unroll
    for (int i = 0; i < 4; i++) {
#pragma unroll
        for (int rr = 0; rr < 2; rr++) {
            int mloc = wm * 64 + i * 16 + rr * 8 + g;
            if (m0 + mloc < cnt) {
                int p = sPair[mloc];
                float* dst = C + (size_t)p * CLD + n0 + wn * 32 + tg * 2;
#pragma unroll
                for (int j = 0; j < 4; j++) {
                    float2 v;
                    v.x = acc[i][j][rr * 2 + 0];
                    v.y = acc[i][j][rr * 2 + 1];
                    *(float2*)(dst + j * 8) = v;
                }
            }
        }
    }
}

// ---------------- act: silu(g) * u  (float4) --------------------------------
__global__ void act_kernel() {
    int i4 = blockIdx.x * blockDim.x + threadIdx.x;       // over NPAIR*FFND/4
    int p  = i4 >> 10;                                    // / (FFND/4)
    int f4 = i4 & 1023;
    if (p >= NPAIR) return;
    const float4* gp = (const float4*)(d_z + (size_t)p * NF2) + f4;
    const float4* up = (const float4*)(d_z + (size_t)p * NF2 + FFND) + f4;
    float4 gv = *gp, uv = *up, r;
    r.x = gv.x / (1.0f + __expf(-gv.x)) * uv.x;
    r.y = gv.y / (1.0f + __expf(-gv.y)) * uv.y;
    r.z = gv.z / (1.0f + __expf(-gv.z)) * uv.z;
    r.w = gv.w / (1.0f + __expf(-gv.w)) * uv.w;
    ((float4*)(d_actbuf + (size_t)p * FFND))[f4] = r;
}

// ---------------- combine: out[t] = w0*y[2t] + w1*y[2t+1] -------------------
__global__ void combine_kernel(float* __restrict__ out) {
    int i4 = blockIdx.x * blockDim.x + threadIdx.x;   // over T*H/4
    int t  = i4 >> 8;                                 // / (HDIM/4)
    int h4 = i4 & 255;
    if (t >= T_TOK) return;
    float w0 = d_wgt[2 * t], w1 = d_wgt[2 * t + 1];
    const float4* y0 = (const float4*)(d_y + (size_t)(2 * t) * HDIM) + h4;
    const float4* y1 = (const float4*)(d_y + (size_t)(2 * t + 1) * HDIM) + h4;
    float4 a = *y0, b = *y1, r;
    r.x = w0 * a.x + w1 * b.x;
    r.y = w0 * a.y + w1 * b.y;
    r.z = w0 * a.z + w1 * b.z;
    r.w = w0 * a.w + w1 * b.w;
    ((float4*)(out + (size_t)t * HDIM))[h4] = r;
}

// ---------------------------------------------------------------------------
extern "C" void kernel_launch(void* const* d_in, const int* in_sizes, int n_in,
                              void* d_out, int out_size) {
    const float* x   = (const float*)d_in[0];  // [2048, 1024]
    const float* gw  = (const float*)d_in[1];  // [8, 1024]
    const float* w13 = (const float*)d_in[2];  // [8, 8192, 1024]
    const float* w2  = (const float*)d_in[3];  // [8, 1024, 4096]
    float* out = (float*)d_out;                // [2048*1024] then [2048*8]
    float* rlogits = out + (size_t)T_TOK * HDIM;

    zero_counts_kernel<<<1, 32>>>();
    router_kernel<<<T_TOK / 8, 256>>>(x, gw, rlogits);

    // GEMM1 (tf32 mma): z[pair, 0..8192) = x[token] . w13[e]^T, K=1024
    dim3 g1(T_TOK / 128, NF2 / 128, NE);      // (16, 64, 8)
    mma_gemm_kernel<HDIM, NF2, 0><<<g1, 256>>>(x, w13);

    act_kernel<<<(NPAIR * FFND / 4) / 256, 256>>>();

    // GEMM2 (tf32 mma): y[pair, 0..1024) = act[pair] . w2[e]^T, K=4096
    dim3 g2(T_TOK / 128, HDIM / 128, NE);     // (16, 8, 8)
    mma_gemm_kernel<FFND, HDIM, 1><<<g2, 256>>>(nullptr, w2);

    combine_kernel<<<(T_TOK * HDIM / 4) / 256, 256>>>(out);
}